// round 1
// baseline (speedup 1.0000x reference)
#include <cuda_runtime.h>
#include <cuda_bf16.h>

#define D_IN   592
#define NBATCH 8192
#define FB     8
#define NT     128
#define C1LEN  295   // (592-3)/2+1
#define P1LEN  147   // (295-3)/2+1
#define C2LEN  73    // (147-3)/2+1
#define P2LEN  36    // (73-3)/2+1
#define DV     148   // 592/4 float4s per row

__global__ void __launch_bounds__(NT) fbank_kernel(
    const float* __restrict__ x,
    const float* __restrict__ c1w, const float* __restrict__ c1b,
    const float* __restrict__ c2w, const float* __restrict__ c2b,
    const float* __restrict__ l1w, const float* __restrict__ l1b,
    const float* __restrict__ l2w, const float* __restrict__ l2b,
    const float* __restrict__ l3w, const float* __restrict__ l3b,
    float* __restrict__ outH, float* __restrict__ outXF,
    float* __restrict__ outXS, float* __restrict__ outF0)
{
    __shared__ __align__(16) float s_xa[D_IN];     // x_aux for current bank
    __shared__ __align__(16) float s_fs[D_IN];     // running filtered_sum
    __shared__ float s_c1[3 * C1LEN];              // conv1 out (885)
    __shared__ float s_p1[3 * P1LEN];              // pool1+relu (441)
    __shared__ float s_c2[C2LEN];
    __shared__ float s_p2[P2LEN];
    __shared__ float s_h1[20];
    __shared__ float s_h2[10];
    __shared__ float s_f0;
    // small weights cached in shared (lin1_w stays in L2: 20 threads x 36 reads)
    __shared__ float s_w1[FB * 9];   // conv1_w [F,3,1,3]
    __shared__ float s_b1[FB * 3];
    __shared__ float s_w2[FB * 9];   // conv2_w [F,1,3,3]
    __shared__ float s_b2[FB];
    __shared__ float s_l1b[FB * 20];
    __shared__ float s_l2w[FB * 200];
    __shared__ float s_l2b[FB * 10];
    __shared__ float s_l3w[FB * 10];
    __shared__ float s_l3b[FB];

    const int tid = threadIdx.x;
    const int b   = blockIdx.x;

    // ---- preload weights ----
    for (int k = tid; k < FB * 9;   k += NT) { s_w1[k] = c1w[k]; s_w2[k] = c2w[k]; }
    for (int k = tid; k < FB * 3;   k += NT) s_b1[k] = c1b[k];
    for (int k = tid; k < FB * 20;  k += NT) s_l1b[k] = l1b[k];
    for (int k = tid; k < FB * 200; k += NT) s_l2w[k] = l2w[k];
    for (int k = tid; k < FB * 10;  k += NT) { s_l2b[k] = l2b[k]; s_l3w[k] = l3w[k]; }
    if (tid < FB) { s_b2[tid] = c2b[tid]; s_l3b[tid] = l3b[tid]; }

    const float4* x4 = (const float4*)(x + (size_t)b * D_IN);
    float4* fs4 = (float4*)s_fs;
    float4* xa4 = (float4*)s_xa;

    for (int v = tid; v < DV; v += NT) fs4[v] = make_float4(0.f, 0.f, 0.f, 0.f);
    __syncthreads();

    for (int i = 0; i < FB; ++i) {
        const size_t row = ((size_t)i * NBATCH + b) * D_IN;

        // ---- x_aux = x - filtered_sum ; emit xs ----
        float4* xs4 = (float4*)(outXS + row);
        for (int v = tid; v < DV; v += NT) {
            float4 xv = x4[v];
            float4 fv = fs4[v];
            float4 a  = make_float4(xv.x - fv.x, xv.y - fv.y, xv.z - fv.z, xv.w - fv.w);
            xa4[v] = a;
            xs4[v] = a;
        }
        __syncthreads();

        // ---- conv1: 3 out-channels, k=3, stride 2 ----
        {
            const float* w1 = s_w1 + i * 9;
            const float* b1 = s_b1 + i * 3;
            for (int idx = tid; idx < 3 * C1LEN; idx += NT) {
                int o = idx / C1LEN;
                int t = idx - o * C1LEN;
                const float* wo = w1 + o * 3;
                float v = fmaf(s_xa[2*t], wo[0],
                          fmaf(s_xa[2*t+1], wo[1],
                          fmaf(s_xa[2*t+2], wo[2], b1[o])));
                s_c1[idx] = v;
            }
        }
        __syncthreads();

        // ---- maxpool3s2 + relu ----
        for (int idx = tid; idx < 3 * P1LEN; idx += NT) {
            int o = idx / P1LEN;
            int t = idx - o * P1LEN;
            const float* c = s_c1 + o * C1LEN + 2 * t;
            float m = fmaxf(fmaxf(c[0], c[1]), c[2]);
            s_p1[idx] = fmaxf(m, 0.0f);
        }
        __syncthreads();

        // ---- conv2: 1 out-channel, 3 in-channels, k=3, stride 2 ----
        {
            const float* w2 = s_w2 + i * 9;
            const float bb = s_b2[i];
            for (int t = tid; t < C2LEN; t += NT) {
                float acc = bb;
                #pragma unroll
                for (int c = 0; c < 3; ++c) {
                    const float* p = s_p1 + c * P1LEN + 2 * t;
                    const float* w = w2 + c * 3;
                    acc = fmaf(p[0], w[0], fmaf(p[1], w[1], fmaf(p[2], w[2], acc)));
                }
                s_c2[t] = acc;
            }
        }
        __syncthreads();

        // ---- maxpool3s2 + relu ----
        for (int t = tid; t < P2LEN; t += NT) {
            float m = fmaxf(fmaxf(s_c2[2*t], s_c2[2*t+1]), s_c2[2*t+2]);
            s_p2[t] = fmaxf(m, 0.0f);
        }
        __syncthreads();

        // ---- lin1: 36 -> 20 (weights from gmem/L2) ----
        if (tid < 20) {
            const float* w = l1w + ((size_t)i * 20 + tid) * 36;
            float acc = s_l1b[i * 20 + tid];
            #pragma unroll
            for (int k = 0; k < 36; ++k) acc = fmaf(s_p2[k], w[k], acc);
            s_h1[tid] = fmaxf(acc, 0.0f);
        }
        __syncthreads();

        // ---- lin2: 20 -> 10 ----
        if (tid < 10) {
            const float* w = s_l2w + (i * 10 + tid) * 20;
            float acc = s_l2b[i * 10 + tid];
            #pragma unroll
            for (int k = 0; k < 20; ++k) acc = fmaf(s_h1[k], w[k], acc);
            s_h2[tid] = fmaxf(acc, 0.0f);
        }
        __syncthreads();

        // ---- lin3: 10 -> 1, sigmoid, f0 ----
        if (tid == 0) {
            const float* w = s_l3w + i * 10;
            float acc = s_l3b[i];
            #pragma unroll
            for (int k = 0; k < 10; ++k) acc = fmaf(s_h2[k], w[k], acc);
            float sg = 1.0f / (1.0f + __expf(-acc));
            float f0 = (float)D_IN * sg;
            s_f0 = f0;
            outF0[(size_t)i * NBATCH + b] = f0;
        }
        __syncthreads();

        const float f0 = s_f0;
        const float inv2w2 = 0.02f;  // 1/(2*5*5)

        // ---- H = exp(-(d-f0)^2/50); xf = xa*H; fs += xf ; emit H, xf ----
        float4* H4  = (float4*)(outH  + row);
        float4* XF4 = (float4*)(outXF + row);
        for (int v = tid; v < DV; v += NT) {
            float4 a  = xa4[v];
            float4 fv = fs4[v];
            float d0 = (float)(4 * v) - f0;
            float d1 = d0 + 1.0f, d2 = d0 + 2.0f, d3 = d0 + 3.0f;
            float4 H;
            H.x = __expf(-d0 * d0 * inv2w2);
            H.y = __expf(-d1 * d1 * inv2w2);
            H.z = __expf(-d2 * d2 * inv2w2);
            H.w = __expf(-d3 * d3 * inv2w2);
            float4 xf = make_float4(a.x * H.x, a.y * H.y, a.z * H.z, a.w * H.w);
            fv.x += xf.x; fv.y += xf.y; fv.z += xf.z; fv.w += xf.w;
            fs4[v] = fv;
            H4[v]  = H;
            XF4[v] = xf;
        }
        __syncthreads();
    }
}

extern "C" void kernel_launch(void* const* d_in, const int* in_sizes, int n_in,
                              void* d_out, int out_size) {
    const float* x   = (const float*)d_in[0];
    const float* c1w = (const float*)d_in[1];
    const float* c1b = (const float*)d_in[2];
    const float* c2w = (const float*)d_in[3];
    const float* c2b = (const float*)d_in[4];
    const float* l1w = (const float*)d_in[5];
    const float* l1b = (const float*)d_in[6];
    const float* l2w = (const float*)d_in[7];
    const float* l2b = (const float*)d_in[8];
    const float* l3w = (const float*)d_in[9];
    const float* l3b = (const float*)d_in[10];

    float* out = (float*)d_out;
    const size_t FBD = (size_t)FB * NBATCH * D_IN;
    float* outH  = out;
    float* outXF = out + FBD;
    float* outXS = out + 2 * FBD;
    float* outF0 = out + 3 * FBD;

    fbank_kernel<<<NBATCH, NT>>>(x, c1w, c1b, c2w, c2b, l1w, l1b,
                                 l2w, l2b, l3w, l3b,
                                 outH, outXF, outXS, outF0);
}